// round 4
// baseline (speedup 1.0000x reference)
#include <cuda_runtime.h>
#include <cuda_fp16.h>
#include <cstdint>

#define B_   8192
#define N_   40
#define F_   256
#define NF   10240
#define TOT  83886080

// ---------------- device scratch (no allocation allowed) --------------------
__device__ __align__(256) __half g_Ahi[TOT];
__device__ __align__(256) __half g_Alo[TOT];
__device__ __align__(256) __half g_Whi[F_ * F_];       // K-major [fout][fin]
__device__ float g_mApart[256 * 40 * 256];             // [group][n][k]
__device__ float g_meanA[40 * 256];
__device__ float g_Mpart[40 * 3 * 4 * 16384];          // [n][tile][kc][128x128]
__device__ float g_M[40 * 65536];                      // [n][j][k]
__device__ float g_scale[NF];
__device__ float g_shift[NF];

// ---------------- helpers ---------------------------------------------------
__device__ __forceinline__ uint32_t smem_u32(const void* p) {
    uint32_t a;
    asm("{ .reg .u64 t; cvta.to.shared.u64 t, %1; cvt.u32.u64 %0, t; }" : "=r"(a) : "l"(p));
    return a;
}
__device__ __forceinline__ void cp16(uint32_t dst, const void* src) {
    asm volatile("cp.async.cg.shared.global [%0], [%1], 16;" :: "r"(dst), "l"(src));
}
#define CP_COMMIT() asm volatile("cp.async.commit_group;" ::: "memory")
#define CP_WAIT(n)  asm volatile("cp.async.wait_group %0;" :: "n"(n) : "memory")

#define LDSM4(r, addr)                                                          \
    asm volatile("ldmatrix.sync.aligned.m8n8.x4.shared.b16 {%0,%1,%2,%3}, [%4];"\
        : "=r"((r)[0]), "=r"((r)[1]), "=r"((r)[2]), "=r"((r)[3]) : "r"(addr))

#define LDSM4T(r, addr)                                                         \
    asm volatile("ldmatrix.sync.aligned.m8n8.x4.trans.shared.b16 {%0,%1,%2,%3}, [%4];"\
        : "=r"((r)[0]), "=r"((r)[1]), "=r"((r)[2]), "=r"((r)[3]) : "r"(addr))

#define MMA(c, a, b)                                                            \
    asm volatile("mma.sync.aligned.m16n8k16.row.col.f32.f16.f16.f32 "           \
        "{%0,%1,%2,%3}, {%4,%5,%6,%7}, {%8,%9}, {%0,%1,%2,%3};"                 \
        : "+f"((c)[0]), "+f"((c)[1]), "+f"((c)[2]), "+f"((c)[3])                \
        : "r"((a)[0]), "r"((a)[1]), "r"((a)[2]), "r"((a)[3]),                   \
          "r"((b)[0]), "r"((b)[1]))

// ---------------------------------------------------------------------------
// K0: W [fin][fout] fp32 -> Whi fp16 K-major [fout][fin]
// ---------------------------------------------------------------------------
__global__ void k0_wprep(const float* __restrict__ W) {
    int k = blockIdx.x, n = threadIdx.x;
    g_Whi[n * 256 + k] = __float2half_rn(W[k * 256 + n]);
}

// ---------------------------------------------------------------------------
// K1: blockdiag bmm -> fp16 hi/lo + meanA partial sums.
// grid (4 blocks, 256 groups), 256 threads; CTA handles 32 batches x 10 rows.
// ---------------------------------------------------------------------------
__global__ void k1_blockdiag(const float* __restrict__ input,
                             const float* __restrict__ adj) {
    const int s = blockIdx.x * 10;
    const int grp = blockIdx.y;
    const int f = threadIdx.x;

    __shared__ float sadj[10][10];
    float msum[10];
#pragma unroll
    for (int r = 0; r < 10; ++r) msum[r] = 0.f;

    for (int bi = 0; bi < 32; ++bi) {
        const int b = grp * 32 + bi;
        __syncthreads();
        if (f < 100)
            sadj[f / 10][f % 10] = adj[((size_t)b * 40 + s + f / 10) * 40 + s + f % 10];
        __syncthreads();

        const float* ip = input + ((size_t)b * 40 + s) * 256 + f;
        float x[10];
#pragma unroll
        for (int c = 0; c < 10; ++c) x[c] = ip[c * 256];

        const size_t ob = ((size_t)b * 40 + s) * 256 + f;
#pragma unroll
        for (int r = 0; r < 10; ++r) {
            float acc = 0.f;
#pragma unroll
            for (int c = 0; c < 10; ++c) acc = fmaf(sadj[r][c], x[c], acc);
            msum[r] += acc;
            __half h = __float2half_rn(acc);
            g_Ahi[ob + (size_t)r * 256] = h;
            g_Alo[ob + (size_t)r * 256] = __float2half_rn(acc - __half2float(h));
        }
    }
    float* mp = g_mApart + ((size_t)grp * 40 + s) * 256 + f;
#pragma unroll
    for (int r = 0; r < 10; ++r) mp[r * 256] = msum[r];
}

// K1b: fold meanA partials. grid 40, 256 threads.
__global__ void k1b_meanA() {
    const int n = blockIdx.x, f = threadIdx.x;
    float sum = 0.f;
    for (int g = 0; g < 256; ++g) sum += g_mApart[((size_t)g * 40 + n) * 256 + f];
    g_meanA[n * 256 + f] = sum * (1.f / (float)B_);
}

// ---------------------------------------------------------------------------
// KM: per-n second moment M_n = A_n^T A_n (fp16 split, 3 passes: HH+HL+LH).
// grid (40 n, 3 tiles: (0,0),(0,1),(1,1), 4 k-chunks of 2048 batches).
// CTA: 128x128 output tile, 8 warps (32m x 64n), batch-chunks of 64.
// smem buffer 64KB: [mHi 16K][mLo 16K][nHi 16K][nLo 16K], double-buffered.
// A^T operand + B operand both via ldmatrix.trans from [b][fin] tiles.
// ---------------------------------------------------------------------------
#define SMEM_KM 131072

__global__ __launch_bounds__(256, 1) void kM_moment() {
    extern __shared__ char smem[];
    const uint32_t sb = smem_u32(smem);
    const int tid = threadIdx.x, lane = tid & 31, wid = tid >> 5;
    const int wr = wid >> 1, wc = wid & 1;
    const int n = blockIdx.x, tile = blockIdx.y, kc = blockIdx.z;
    const int mbase = (tile == 2) ? 128 : 0;
    const int nbase = (tile == 0) ? 0 : 128;
    const bool diag = (tile != 1);
    const uint32_t nOff = diag ? 0u : 32768u;

    const char* hiP = (const char*)g_Ahi + (size_t)n * 512;
    const char* loP = (const char*)g_Alo + (size_t)n * 512;
    const int b00 = kc * 2048;

    auto loadChunk = [&](int bc, int buf) {
        const uint32_t s0 = sb + buf * 65536;
        const size_t gb = (size_t)(b00 + bc * 64) * 20480;
#pragma unroll
        for (int it = 0; it < 4; ++it) {
            int u = it * 256 + tid;
            int bl = u >> 4, un = u & 15;
            size_t g = gb + (size_t)bl * 20480 + un * 16;
            uint32_t so = bl * 256 + ((un ^ (bl & 7)) << 4);
            cp16(s0 + so,         hiP + g + mbase * 2);
            cp16(s0 + 16384 + so, loP + g + mbase * 2);
            if (!diag) {
                cp16(s0 + 32768 + so, hiP + g + nbase * 2);
                cp16(s0 + 49152 + so, loP + g + nbase * 2);
            }
        }
    };

    float acc[2][8][4];
#pragma unroll
    for (int mt = 0; mt < 2; ++mt)
#pragma unroll
        for (int nt = 0; nt < 8; ++nt)
#pragma unroll
            for (int q = 0; q < 4; ++q) acc[mt][nt][q] = 0.f;

    loadChunk(0, 0);
    CP_COMMIT();

    int buf = 0;
    for (int bc = 0; bc < 32; ++bc) {
        if (bc < 31) {
            loadChunk(bc + 1, buf ^ 1);
            CP_COMMIT();
            CP_WAIT(1);
        } else {
            CP_WAIT(0);
        }
        __syncthreads();
        const uint32_t s0 = sb + buf * 65536;
#pragma unroll
        for (int kk = 0; kk < 4; ++kk) {
            // A^T fragments (m = fin, k = batch) via trans loads
            uint32_t ahi[2][4], alo[2][4];
            const int krA = kk * 16 + (lane & 7) + ((lane >> 4) << 3);
#pragma unroll
            for (int mt = 0; mt < 2; ++mt) {
                int mu = wr * 4 + mt * 2 + ((lane >> 3) & 1);
                uint32_t off = (uint32_t)krA * 256 + ((mu ^ (krA & 7)) << 4);
                LDSM4T(ahi[mt], s0 + off);
                LDSM4T(alo[mt], s0 + 16384 + off);
            }
            // B fragments (k = batch, n = fin) via trans loads
            uint32_t bhi[8][2], blo[8][2];
            const int krB = kk * 16 + (lane & 7) + (((lane >> 3) & 1) << 3);
#pragma unroll
            for (int p = 0; p < 4; ++p) {
                int nu = wc * 8 + p * 2 + (lane >> 4);
                uint32_t off = (uint32_t)krB * 256 + ((nu ^ (krB & 7)) << 4);
                uint32_t r[4];
                LDSM4T(r, s0 + nOff + off);
                bhi[2 * p][0] = r[0]; bhi[2 * p][1] = r[1];
                bhi[2 * p + 1][0] = r[2]; bhi[2 * p + 1][1] = r[3];
                LDSM4T(r, s0 + nOff + 16384 + off);
                blo[2 * p][0] = r[0]; blo[2 * p][1] = r[1];
                blo[2 * p + 1][0] = r[2]; blo[2 * p + 1][1] = r[3];
            }
#pragma unroll
            for (int mt = 0; mt < 2; ++mt)
#pragma unroll
                for (int nt = 0; nt < 8; ++nt) MMA(acc[mt][nt], ahi[mt], bhi[nt]);
#pragma unroll
            for (int mt = 0; mt < 2; ++mt)
#pragma unroll
                for (int nt = 0; nt < 8; ++nt) MMA(acc[mt][nt], ahi[mt], blo[nt]);
#pragma unroll
            for (int mt = 0; mt < 2; ++mt)
#pragma unroll
                for (int nt = 0; nt < 8; ++nt) MMA(acc[mt][nt], alo[mt], bhi[nt]);
        }
        __syncthreads();
        buf ^= 1;
    }

    float* P = g_Mpart + (size_t)((n * 3 + tile) * 4 + kc) * 16384;
    const int r0 = wr * 32 + (lane >> 2);
    const int c0 = wc * 64 + (lane & 3) * 2;
#pragma unroll
    for (int mt = 0; mt < 2; ++mt)
#pragma unroll
        for (int nt = 0; nt < 8; ++nt) {
            *(float2*)(P + (r0 + mt * 16) * 128 + c0 + nt * 8) =
                make_float2(acc[mt][nt][0], acc[mt][nt][1]);
            *(float2*)(P + (r0 + mt * 16 + 8) * 128 + c0 + nt * 8) =
                make_float2(acc[mt][nt][2], acc[mt][nt][3]);
        }
}

// KMr: fold kc partials + symmetric fill -> g_M[n][j][k]. grid (64, 40).
__global__ void kMr_reduce() {
    const int n = blockIdx.y;
    const int idx = blockIdx.x * 256 + threadIdx.x;   // 16384 threads
#pragma unroll
    for (int e = 0; e < 4; ++e) {
        int jk = e * 16384 + idx;
        int j = jk >> 8, k = jk & 255;
        int jt = j >> 7, kt = k >> 7, jl = j & 127, kl = k & 127;
        int tile, r, c;
        if (jt == 0 && kt == 0)      { tile = 0; r = jl; c = kl; }
        else if (jt == 0)            { tile = 1; r = jl; c = kl; }
        else if (kt == 1)            { tile = 2; r = jl; c = kl; }
        else                         { tile = 1; r = kl; c = jl; }  // transpose
        const float* P = g_Mpart + (size_t)(n * 3 + tile) * 4 * 16384 + r * 128 + c;
        g_M[(size_t)n * 65536 + jk] = P[0] + P[16384] + P[32768] + P[49152];
    }
}

// ---------------------------------------------------------------------------
// KS: scale/shift per (n,f).  E[Y^2] = (w_f^T M_n w_f)/B;  meanY = meanA @ W.
// grid (40, 8 f-chunks of 32), 256 threads = (32 f, 8 j-groups).
// ---------------------------------------------------------------------------
__global__ void kS_stats(const float* __restrict__ W,
                         const float* __restrict__ gamma,
                         const float* __restrict__ beta) {
    const int n = blockIdx.x;
    const int f = blockIdx.y * 32 + (threadIdx.x & 31);
    const int jg = threadIdx.x >> 5;
    const float* Mn = g_M + (size_t)n * 65536;
    const float* Wf = W + f;

    float acc = 0.f;
    for (int j = jg * 32; j < jg * 32 + 32; ++j) {
        const float* Mr = Mn + j * 256;
        float t0 = 0.f, t1 = 0.f, t2 = 0.f, t3 = 0.f;
#pragma unroll 4
        for (int k = 0; k < 256; k += 4) {
            t0 = fmaf(Mr[k],     Wf[(k)     * 256], t0);
            t1 = fmaf(Mr[k + 1], Wf[(k + 1) * 256], t1);
            t2 = fmaf(Mr[k + 2], Wf[(k + 2) * 256], t2);
            t3 = fmaf(Mr[k + 3], Wf[(k + 3) * 256], t3);
        }
        acc = fmaf(Wf[j * 256], (t0 + t1) + (t2 + t3), acc);
    }
    __shared__ float red[8][33];
    red[jg][threadIdx.x & 31] = acc;
    __syncthreads();
    if (jg == 0) {
        float s = 0.f;
#pragma unroll
        for (int g = 0; g < 8; ++g) s += red[g][threadIdx.x & 31];
        float E2 = s * (1.f / (float)B_);
        float mY = 0.f;
        for (int k = 0; k < 256; ++k)
            mY = fmaf(g_meanA[n * 256 + k], Wf[k * 256], mY);
        float var = fmaxf(E2 - mY * mY, 0.f);
        int nf = n * 256 + f;
        int blk = n / 10;
        float sc = gamma[blk * NF + nf] * rsqrtf(var + 1e-5f);
        float bsum = beta[nf] + beta[NF + nf] + beta[2 * NF + nf] + beta[3 * NF + nf];
        g_scale[nf] = sc;
        g_shift[nf] = fmaf(-mY, sc, bsum);
    }
}

// ---------------------------------------------------------------------------
// KF: fused GEMM + normalize.  out = (A @ Whi) * scale + shift, fp16 2-pass
// (Ahi*Whi + Alo*Whi = exact A*Whi).  CTA 128x128, BK=64, double-buffered.
// smem buffer 48KB: [Ahi 16K][Alo 16K][Bhi 16K].
// ---------------------------------------------------------------------------
#define SMEM_KF 98304

__global__ __launch_bounds__(256, 1) void kF_gemm_norm(float* __restrict__ out) {
    extern __shared__ char smem[];
    const uint32_t sb = smem_u32(smem);
    const int tid = threadIdx.x, lane = tid & 31, wid = tid >> 5;
    const int wr = wid >> 1, wc = wid & 1;
    const int rowBase = (blockIdx.x >> 1) * 128;
    const int colBase = (blockIdx.x & 1) * 128;

    const char* aH = (const char*)g_Ahi + (size_t)rowBase * 512;
    const char* aL = (const char*)g_Alo + (size_t)rowBase * 512;
    const char* bH = (const char*)g_Whi + (size_t)colBase * 512;

    auto loadChunk = [&](int kcc, int buf) {
        const uint32_t s0 = sb + buf * 49152;
#pragma unroll
        for (int it = 0; it < 4; ++it) {
            int u = it * 256 + tid;
            int r = u >> 3, o = u & 7;
            size_t g = (size_t)r * 512 + (size_t)kcc * 128 + o * 16;
            uint32_t so = r * 128 + ((o ^ (r & 7)) << 4);
            cp16(s0 + so,         aH + g);
            cp16(s0 + 16384 + so, aL + g);
            cp16(s0 + 32768 + so, bH + g);
        }
    };

    float acc[2][8][4];
#pragma unroll
    for (int mt = 0; mt < 2; ++mt)
#pragma unroll
        for (int nt = 0; nt < 8; ++nt)
#pragma unroll
            for (int q = 0; q < 4; ++q) acc[mt][nt][q] = 0.f;

    loadChunk(0, 0);
    CP_COMMIT();

    const int aRow0 = wr * 32 + (lane & 15);
    const int aKU = lane >> 4;
    const int aSw = lane & 7;
    const int bN0 = wc * 64 + (lane & 7) + ((lane >> 4) & 1) * 8;
    const int bKU = (lane >> 3) & 1;

    int buf = 0;
#pragma unroll
    for (int kcc = 0; kcc < 4; ++kcc) {
        if (kcc < 3) {
            loadChunk(kcc + 1, buf ^ 1);
            CP_COMMIT();
            CP_WAIT(1);
        } else {
            CP_WAIT(0);
        }
        __syncthreads();
        const uint32_t s0 = sb + buf * 49152;
#pragma unroll
        for (int kk = 0; kk < 4; ++kk) {
            uint32_t ahi[2][4], alo[2][4];
#pragma unroll
            for (int mt = 0; mt < 2; ++mt) {
                uint32_t off = (uint32_t)(aRow0 + mt * 16) * 128 +
                               (uint32_t)(((kk * 2 + aKU) ^ aSw) << 4);
                LDSM4(ahi[mt], s0 + off);
                LDSM4(alo[mt], s0 + 16384 + off);
            }
            uint32_t bf[8][2];
#pragma unroll
            for (int p = 0; p < 4; ++p) {
                uint32_t off = (uint32_t)(bN0 + p * 16) * 128 +
                               (uint32_t)(((kk * 2 + bKU) ^ aSw) << 4);
                uint32_t r[4];
                LDSM4(r, s0 + 32768 + off);
                bf[2 * p][0] = r[0]; bf[2 * p][1] = r[1];
                bf[2 * p + 1][0] = r[2]; bf[2 * p + 1][1] = r[3];
            }
#pragma unroll
            for (int mt = 0; mt < 2; ++mt)
#pragma unroll
                for (int nt = 0; nt < 8; ++nt) MMA(acc[mt][nt], ahi[mt], bf[nt]);
#pragma unroll
            for (int mt = 0; mt < 2; ++mt)
#pragma unroll
                for (int nt = 0; nt < 8; ++nt) MMA(acc[mt][nt], alo[mt], bf[nt]);
        }
        __syncthreads();
        buf ^= 1;
    }

    // fused normalize epilogue
    const int erow = wr * 32 + (lane >> 2);
    const int ecol = colBase + wc * 64 + (lane & 3) * 2;
#pragma unroll
    for (int mt = 0; mt < 2; ++mt) {
#pragma unroll
        for (int h = 0; h < 2; ++h) {
            const int grow = rowBase + erow + mt * 16 + h * 8;
            const int nn = grow % 40;
            const float* scp = g_scale + nn * 256;
            const float* shp = g_shift + nn * 256;
            float* op = out + (size_t)grow * 256;
#pragma unroll
            for (int nt = 0; nt < 8; ++nt) {
                const int fc = ecol + nt * 8;
                float2 sc = *(const float2*)(scp + fc);
                float2 sh = *(const float2*)(shp + fc);
                float2 o2;
                o2.x = fmaf(acc[mt][nt][2 * h + 0], sc.x, sh.x);
                o2.y = fmaf(acc[mt][nt][2 * h + 1], sc.y, sh.y);
                *(float2*)(op + fc) = o2;
            }
        }
    }
}

// ---------------------------------------------------------------------------
extern "C" void kernel_launch(void* const* d_in, const int* in_sizes, int n_in,
                              void* d_out, int out_size) {
    const float* input = (const float*)d_in[0];
    const float* adj   = (const float*)d_in[1];
    const float* W     = (const float*)d_in[2];
    const float* gamma = (const float*)d_in[3];
    const float* beta  = (const float*)d_in[4];
    float* out = (float*)d_out;

    static bool attr_set = false;
    if (!attr_set) {
        cudaFuncSetAttribute(kM_moment, cudaFuncAttributeMaxDynamicSharedMemorySize, SMEM_KM);
        cudaFuncSetAttribute(kF_gemm_norm, cudaFuncAttributeMaxDynamicSharedMemorySize, SMEM_KF);
        attr_set = true;
    }

    k0_wprep<<<256, 256>>>(W);
    k1_blockdiag<<<dim3(4, 256), 256>>>(input, adj);
    k1b_meanA<<<40, 256>>>();
    kM_moment<<<dim3(40, 3, 4), 256, SMEM_KM>>>();
    kMr_reduce<<<dim3(64, 40), 256>>>();
    kS_stats<<<dim3(40, 8), 256>>>(W, gamma, beta);
    kF_gemm_norm<<<5120, 256, SMEM_KF>>>(out);
}

// round 5
// speedup vs baseline: 2.0776x; 2.0776x over previous
#include <cuda_runtime.h>
#include <cuda_fp16.h>
#include <cstdint>

#define B_   8192
#define N_   40
#define F_   256
#define NF   10240
#define TOT  83886080

// ---------------- device scratch (no allocation allowed) --------------------
__device__ __align__(256) __half g_Ahi[TOT];
__device__ __align__(256) __half g_Alo[TOT];
__device__ __align__(256) __half g_Whi[F_ * F_];   // K-major [fout][fin]
__device__ float g_sp[40 * 64 * 2 * 2 * 128];      // [n][bg][ct][stat][col]
__device__ float g_scale[NF];
__device__ float g_shift[NF];

// ---------------- helpers ---------------------------------------------------
__device__ __forceinline__ uint32_t smem_u32(const void* p) {
    uint32_t a;
    asm("{ .reg .u64 t; cvta.to.shared.u64 t, %1; cvt.u32.u64 %0, t; }" : "=r"(a) : "l"(p));
    return a;
}
__device__ __forceinline__ void cp16(uint32_t dst, const void* src) {
    asm volatile("cp.async.cg.shared.global [%0], [%1], 16;" :: "r"(dst), "l"(src));
}
#define CP_COMMIT() asm volatile("cp.async.commit_group;" ::: "memory")
#define CP_WAIT(n)  asm volatile("cp.async.wait_group %0;" :: "n"(n) : "memory")

#define LDSM4(r, addr)                                                          \
    asm volatile("ldmatrix.sync.aligned.m8n8.x4.shared.b16 {%0,%1,%2,%3}, [%4];"\
        : "=r"((r)[0]), "=r"((r)[1]), "=r"((r)[2]), "=r"((r)[3]) : "r"(addr))

#define MMA(c, a, b)                                                            \
    asm volatile("mma.sync.aligned.m16n8k16.row.col.f32.f16.f16.f32 "           \
        "{%0,%1,%2,%3}, {%4,%5,%6,%7}, {%8,%9}, {%0,%1,%2,%3};"                 \
        : "+f"((c)[0]), "+f"((c)[1]), "+f"((c)[2]), "+f"((c)[3])                \
        : "r"((a)[0]), "r"((a)[1]), "r"((a)[2]), "r"((a)[3]),                   \
          "r"((b)[0]), "r"((b)[1]))

// ---------------------------------------------------------------------------
// K0: W [fin][fout] fp32 -> fp16 K-major [fout][fin]
// ---------------------------------------------------------------------------
__global__ void k0_wprep(const float* __restrict__ W) {
    int k = blockIdx.x, n = threadIdx.x;
    g_Whi[n * 256 + k] = __float2half_rn(W[k * 256 + n]);
}

// ---------------------------------------------------------------------------
// K1: blockdiag bmm -> fp16 hi/lo.  grid (4, B_), 256 threads.
// ---------------------------------------------------------------------------
__global__ void k1_blockdiag(const float* __restrict__ input,
                             const float* __restrict__ adj) {
    const int b = blockIdx.y;
    const int s = blockIdx.x * 10;
    const int f = threadIdx.x;

    __shared__ float sadj[10][10];
    if (f < 100)
        sadj[f / 10][f % 10] = adj[((size_t)b * 40 + s + f / 10) * 40 + s + f % 10];
    __syncthreads();

    const float* ip = input + ((size_t)b * 40 + s) * 256 + f;
    float x[10];
#pragma unroll
    for (int c = 0; c < 10; ++c) x[c] = ip[c * 256];

    const size_t ob = ((size_t)b * 40 + s) * 256 + f;
#pragma unroll
    for (int r = 0; r < 10; ++r) {
        float acc = 0.f;
#pragma unroll
        for (int c = 0; c < 10; ++c) acc = fmaf(sadj[r][c], x[c], acc);
        __half h = __float2half_rn(acc);
        g_Ahi[ob + (size_t)r * 256] = h;
        g_Alo[ob + (size_t)r * 256] = __float2half_rn(acc - __half2float(h));
    }
}

// ---------------------------------------------------------------------------
// K2: fp16-split 2-pass HMMA GEMM + fused per-column stats.
// CTA = (n, batch-group of 128, col-half ct). M rows are same-n, batch-strided
// (global row = (bg*128+i)*40 + n, byte stride 40*512 = 20480).
// 8 warps (32m x 64n), BK=64, double-buffered cp.async.
// Epilogue: write Y + per-CTA column (sum, sumsq) partials to g_sp.
// ---------------------------------------------------------------------------
#define SMEM_K2 98304

__global__ __launch_bounds__(256, 1) void k2_gemm_stats(float* __restrict__ Y) {
    extern __shared__ char smem[];
    const uint32_t sb = smem_u32(smem);
    const int tid = threadIdx.x, lane = tid & 31, wid = tid >> 5;
    const int wr = wid >> 1, wc = wid & 1;
    const int n = blockIdx.x;       // 0..39
    const int bg = blockIdx.y;      // 0..63
    const int ct = blockIdx.z;      // 0..1

    const char* aH = (const char*)g_Ahi + ((size_t)bg * 128 * 40 + n) * 512;
    const char* aL = (const char*)g_Alo + ((size_t)bg * 128 * 40 + n) * 512;
    const char* bH = (const char*)g_Whi + (size_t)ct * 128 * 512;

    auto loadChunk = [&](int kcc, int buf) {
        const uint32_t s0 = sb + buf * 49152;
#pragma unroll
        for (int it = 0; it < 4; ++it) {
            int u = it * 256 + tid;
            int r = u >> 3, o = u & 7;
            size_t ga = (size_t)r * 20480 + (size_t)kcc * 128 + o * 16;
            size_t gb = (size_t)r * 512 + (size_t)kcc * 128 + o * 16;
            uint32_t so = r * 128 + ((o ^ (r & 7)) << 4);
            cp16(s0 + so,         aH + ga);
            cp16(s0 + 16384 + so, aL + ga);
            cp16(s0 + 32768 + so, bH + gb);
        }
    };

    float acc[2][8][4];
#pragma unroll
    for (int mt = 0; mt < 2; ++mt)
#pragma unroll
        for (int nt = 0; nt < 8; ++nt)
#pragma unroll
            for (int q = 0; q < 4; ++q) acc[mt][nt][q] = 0.f;

    loadChunk(0, 0);
    CP_COMMIT();

    const int aRow0 = wr * 32 + (lane & 15);
    const int aKU = lane >> 4;
    const int aSw = lane & 7;
    const int bN0 = wc * 64 + (lane & 7) + ((lane >> 4) & 1) * 8;
    const int bKU = (lane >> 3) & 1;

    int buf = 0;
#pragma unroll
    for (int kcc = 0; kcc < 4; ++kcc) {
        if (kcc < 3) {
            loadChunk(kcc + 1, buf ^ 1);
            CP_COMMIT();
            CP_WAIT(1);
        } else {
            CP_WAIT(0);
        }
        __syncthreads();
        const uint32_t s0 = sb + buf * 49152;
#pragma unroll
        for (int kk = 0; kk < 4; ++kk) {
            uint32_t ahi[2][4], alo[2][4];
#pragma unroll
            for (int mt = 0; mt < 2; ++mt) {
                uint32_t off = (uint32_t)(aRow0 + mt * 16) * 128 +
                               (uint32_t)(((kk * 2 + aKU) ^ aSw) << 4);
                LDSM4(ahi[mt], s0 + off);
                LDSM4(alo[mt], s0 + 16384 + off);
            }
            uint32_t bf[8][2];
#pragma unroll
            for (int p = 0; p < 4; ++p) {
                uint32_t off = (uint32_t)(bN0 + p * 16) * 128 +
                               (uint32_t)(((kk * 2 + bKU) ^ aSw) << 4);
                uint32_t r[4];
                LDSM4(r, s0 + 32768 + off);
                bf[2 * p][0] = r[0]; bf[2 * p][1] = r[1];
                bf[2 * p + 1][0] = r[2]; bf[2 * p + 1][1] = r[3];
            }
#pragma unroll
            for (int mt = 0; mt < 2; ++mt)
#pragma unroll
                for (int nt = 0; nt < 8; ++nt) MMA(acc[mt][nt], ahi[mt], bf[nt]);
#pragma unroll
            for (int mt = 0; mt < 2; ++mt)
#pragma unroll
                for (int nt = 0; nt < 8; ++nt) MMA(acc[mt][nt], alo[mt], bf[nt]);
        }
        __syncthreads();
        buf ^= 1;
    }

    // ---- write Y (rows strided by 40*256 floats) ----
    const int rloc = wr * 32 + (lane >> 2);
    const int cloc = wc * 64 + (lane & 3) * 2;
#pragma unroll
    for (int mt = 0; mt < 2; ++mt)
#pragma unroll
        for (int h = 0; h < 2; ++h) {
            const int grow = (bg * 128 + rloc + mt * 16 + h * 8) * 40 + n;
            float* op = Y + (size_t)grow * 256 + ct * 128;
#pragma unroll
            for (int nt = 0; nt < 8; ++nt)
                *(float2*)(op + cloc + nt * 8) =
                    make_float2(acc[mt][nt][2 * h], acc[mt][nt][2 * h + 1]);
        }

    // ---- fused column stats: sum & sumsq over this CTA's 128 rows ----
    float s[8][2], s2[8][2];
#pragma unroll
    for (int nt = 0; nt < 8; ++nt)
#pragma unroll
        for (int c = 0; c < 2; ++c) {
            float v0 = acc[0][nt][c],     v1 = acc[0][nt][2 + c];
            float v2 = acc[1][nt][c],     v3 = acc[1][nt][2 + c];
            s[nt][c] = (v0 + v1) + (v2 + v3);
            s2[nt][c] = fmaf(v0, v0, fmaf(v1, v1, fmaf(v2, v2, v3 * v3)));
        }
    // reduce across the 8 row-subgroups in the warp (lanes differing in bits 2-4)
#pragma unroll
    for (int m = 4; m <= 16; m <<= 1)
#pragma unroll
        for (int nt = 0; nt < 8; ++nt)
#pragma unroll
            for (int c = 0; c < 2; ++c) {
                s[nt][c]  += __shfl_xor_sync(0xFFFFFFFF, s[nt][c], m);
                s2[nt][c] += __shfl_xor_sync(0xFFFFFFFF, s2[nt][c], m);
            }
    // stage warp partials: smem float [8 warps][2 stats][64 cols]
    float* st = (float*)smem;
    __syncthreads();                 // smem buffers no longer needed
    if (lane < 4) {
#pragma unroll
        for (int nt = 0; nt < 8; ++nt)
#pragma unroll
            for (int c = 0; c < 2; ++c) {
                st[(wid * 2 + 0) * 64 + nt * 8 + lane * 2 + c] = s[nt][c];
                st[(wid * 2 + 1) * 64 + nt * 8 + lane * 2 + c] = s2[nt][c];
            }
    }
    __syncthreads();
    if (tid < 128) {
        const int col = tid;              // 0..127 within ct half
        const int wch = col >> 6, ci = col & 63;
        float ts = 0.f, ts2 = 0.f;
#pragma unroll
        for (int w = 0; w < 4; ++w) {
            ts  += st[((w * 2 + wch) * 2 + 0) * 64 + ci];
            ts2 += st[((w * 2 + wch) * 2 + 1) * 64 + ci];
        }
        float* gp = g_sp + (size_t)(((n * 64 + bg) * 2 + ct) * 2) * 128;
        gp[col] = ts;
        gp[128 + col] = ts2;
    }
}

// ---------------------------------------------------------------------------
// K3b: fold bg partials -> scale/shift. grid (40, 2), 128 threads.
// ---------------------------------------------------------------------------
__global__ void k3b_scaleshift(const float* __restrict__ gamma,
                               const float* __restrict__ beta) {
    const int n = blockIdx.x, ct = blockIdx.y, col = threadIdx.x;
    float s = 0.f, s2 = 0.f;
#pragma unroll 4
    for (int bg = 0; bg < 64; ++bg) {
        const float* gp = g_sp + (size_t)(((n * 64 + bg) * 2 + ct) * 2) * 128;
        s += gp[col];
        s2 += gp[128 + col];
    }
    const float inv = 1.f / (float)B_;
    float mean = s * inv;
    float var = fmaxf(s2 * inv - mean * mean, 0.f);
    int nf = n * 256 + ct * 128 + col;
    int blk = n / 10;
    float sc = gamma[blk * NF + nf] * rsqrtf(var + 1e-5f);
    float bsum = beta[nf] + beta[NF + nf] + beta[2 * NF + nf] + beta[3 * NF + nf];
    g_scale[nf] = sc;
    g_shift[nf] = fmaf(-mean, sc, bsum);
}

// ---------------------------------------------------------------------------
// K4: out = Y * scale[nf] + shift[nf], float4.
// ---------------------------------------------------------------------------
__global__ void k4_normalize(float* __restrict__ Y) {
    const size_t gid = (size_t)blockIdx.x * blockDim.x + threadIdx.x;
    const int nf4 = (int)(gid % (NF / 4));
    float4 y = ((const float4*)Y)[gid];
    float4 sc = ((const float4*)g_scale)[nf4];
    float4 sh = ((const float4*)g_shift)[nf4];
    y.x = fmaf(y.x, sc.x, sh.x);
    y.y = fmaf(y.y, sc.y, sh.y);
    y.z = fmaf(y.z, sc.z, sh.z);
    y.w = fmaf(y.w, sc.w, sh.w);
    ((float4*)Y)[gid] = y;
}

// ---------------------------------------------------------------------------
extern "C" void kernel_launch(void* const* d_in, const int* in_sizes, int n_in,
                              void* d_out, int out_size) {
    const float* input = (const float*)d_in[0];
    const float* adj   = (const float*)d_in[1];
    const float* W     = (const float*)d_in[2];
    const float* gamma = (const float*)d_in[3];
    const float* beta  = (const float*)d_in[4];
    float* out = (float*)d_out;

    static bool attr_set = false;
    if (!attr_set) {
        cudaFuncSetAttribute(k2_gemm_stats, cudaFuncAttributeMaxDynamicSharedMemorySize, SMEM_K2);
        attr_set = true;
    }

    k0_wprep<<<256, 256>>>(W);
    k1_blockdiag<<<dim3(4, B_), 256>>>(input, adj);
    k2_gemm_stats<<<dim3(40, 64, 2), 256, SMEM_K2>>>(out);
    k3b_scaleshift<<<dim3(40, 2), 128>>>(gamma, beta);
    k4_normalize<<<(TOT / 4) / 256, 256>>>(out);
}

// round 6
// speedup vs baseline: 2.2027x; 1.0602x over previous
#include <cuda_runtime.h>
#include <cuda_fp16.h>
#include <cstdint>

#define B_   8192
#define N_   40
#define F_   256
#define NF   10240
#define TOT  83886080

// ---------------- device scratch (no allocation allowed) --------------------
__device__ __align__(256) __half g_Ahi[TOT];
__device__ __align__(256) __half g_Alo[TOT];
__device__ __align__(256) __half g_Whi[F_ * F_];   // K-major [fout][fin]
__device__ float g_sp[40 * 64 * 2 * 256];          // [n][bg][stat][col]
__device__ float g_scale[NF];
__device__ float g_shift[NF];

// ---------------- helpers ---------------------------------------------------
__device__ __forceinline__ uint32_t smem_u32(const void* p) {
    uint32_t a;
    asm("{ .reg .u64 t; cvta.to.shared.u64 t, %1; cvt.u32.u64 %0, t; }" : "=r"(a) : "l"(p));
    return a;
}
__device__ __forceinline__ void cp16(uint32_t dst, const void* src) {
    asm volatile("cp.async.cg.shared.global [%0], [%1], 16;" :: "r"(dst), "l"(src));
}
#define CP_COMMIT() asm volatile("cp.async.commit_group;" ::: "memory")
#define CP_WAIT(n)  asm volatile("cp.async.wait_group %0;" :: "n"(n) : "memory")

#define LDSM4(r, addr)                                                          \
    asm volatile("ldmatrix.sync.aligned.m8n8.x4.shared.b16 {%0,%1,%2,%3}, [%4];"\
        : "=r"((r)[0]), "=r"((r)[1]), "=r"((r)[2]), "=r"((r)[3]) : "r"(addr))

#define MMA(c, a, b)                                                            \
    asm volatile("mma.sync.aligned.m16n8k16.row.col.f32.f16.f16.f32 "           \
        "{%0,%1,%2,%3}, {%4,%5,%6,%7}, {%8,%9}, {%0,%1,%2,%3};"                 \
        : "+f"((c)[0]), "+f"((c)[1]), "+f"((c)[2]), "+f"((c)[3])                \
        : "r"((a)[0]), "r"((a)[1]), "r"((a)[2]), "r"((a)[3]),                   \
          "r"((b)[0]), "r"((b)[1]))

// ---------------------------------------------------------------------------
// K0: W [fin][fout] fp32 -> fp16 K-major [fout][fin]
// ---------------------------------------------------------------------------
__global__ void k0_wprep(const float* __restrict__ W) {
    int k = blockIdx.x, n = threadIdx.x;
    g_Whi[n * 256 + k] = __float2half_rn(W[k * 256 + n]);
}

// ---------------------------------------------------------------------------
// K1: blockdiag bmm -> fp16 hi/lo.  grid (4, B_), 256 threads.
// ---------------------------------------------------------------------------
__global__ void k1_blockdiag(const float* __restrict__ input,
                             const float* __restrict__ adj) {
    const int b = blockIdx.y;
    const int s = blockIdx.x * 10;
    const int f = threadIdx.x;

    __shared__ float sadj[10][10];
    if (f < 100)
        sadj[f / 10][f % 10] = adj[((size_t)b * 40 + s + f / 10) * 40 + s + f % 10];
    __syncthreads();

    const float* ip = input + ((size_t)b * 40 + s) * 256 + f;
    float x[10];
#pragma unroll
    for (int c = 0; c < 10; ++c) x[c] = ip[c * 256];

    const size_t ob = ((size_t)b * 40 + s) * 256 + f;
#pragma unroll
    for (int r = 0; r < 10; ++r) {
        float acc = 0.f;
#pragma unroll
        for (int c = 0; c < 10; ++c) acc = fmaf(sadj[r][c], x[c], acc);
        __half h = __float2half_rn(acc);
        g_Ahi[ob + (size_t)r * 256] = h;
        g_Alo[ob + (size_t)r * 256] = __float2half_rn(acc - __half2float(h));
    }
}

// ---------------------------------------------------------------------------
// K2: fp16-split 2-pass HMMA GEMM, full 256 output cols per CTA + fused stats.
// CTA = (n, batch-group of 128). Rows are same-n, batch-strided (20480B).
// 8 warps, warp tile 32m x 128n. BK=64, double-buffered cp.async (2x64KB).
// smem buffer: [Ahi 16K][Alo 16K][B 32K].
// ---------------------------------------------------------------------------
#define SMEM_K2 131072

__global__ __launch_bounds__(256, 1) void k2_gemm_stats(float* __restrict__ Y) {
    extern __shared__ char smem[];
    const uint32_t sb = smem_u32(smem);
    const int tid = threadIdx.x, lane = tid & 31, wid = tid >> 5;
    const int wr = wid >> 1, wc = wid & 1;
    const int n = blockIdx.x;       // 0..39
    const int bg = blockIdx.y;      // 0..63

    const char* aH = (const char*)g_Ahi + ((size_t)bg * 128 * 40 + n) * 512;
    const char* aL = (const char*)g_Alo + ((size_t)bg * 128 * 40 + n) * 512;
    const char* bB = (const char*)g_Whi;

    auto loadChunk = [&](int kcc, int buf) {
        const uint32_t s0 = sb + buf * 65536;
#pragma unroll
        for (int it = 0; it < 4; ++it) {
            int u = it * 256 + tid;
            int r = u >> 3, o = u & 7;
            size_t ga = (size_t)r * 20480 + (size_t)kcc * 128 + o * 16;
            uint32_t so = r * 128 + ((o ^ (r & 7)) << 4);
            cp16(s0 + so,         aH + ga);
            cp16(s0 + 16384 + so, aL + ga);
        }
#pragma unroll
        for (int it = 0; it < 8; ++it) {
            int u = it * 256 + tid;
            int r = u >> 3, o = u & 7;
            size_t gb = (size_t)r * 512 + (size_t)kcc * 128 + o * 16;
            uint32_t so = r * 128 + ((o ^ (r & 7)) << 4);
            cp16(s0 + 32768 + so, bB + gb);
        }
    };

    float acc[2][16][4];
#pragma unroll
    for (int mt = 0; mt < 2; ++mt)
#pragma unroll
        for (int nt = 0; nt < 16; ++nt)
#pragma unroll
            for (int q = 0; q < 4; ++q) acc[mt][nt][q] = 0.f;

    loadChunk(0, 0);
    CP_COMMIT();

    const int aRow0 = wr * 32 + (lane & 15);
    const int aKU = lane >> 4;
    const int aSw = lane & 7;
    const int bN0 = wc * 128 + (lane & 7) + ((lane >> 4) & 1) * 8;
    const int bKU = (lane >> 3) & 1;

    int buf = 0;
#pragma unroll
    for (int kcc = 0; kcc < 4; ++kcc) {
        if (kcc < 3) {
            loadChunk(kcc + 1, buf ^ 1);
            CP_COMMIT();
            CP_WAIT(1);
        } else {
            CP_WAIT(0);
        }
        __syncthreads();
        const uint32_t s0 = sb + buf * 65536;
#pragma unroll
        for (int kk = 0; kk < 4; ++kk) {
            uint32_t ahi[2][4], alo[2][4];
#pragma unroll
            for (int mt = 0; mt < 2; ++mt) {
                uint32_t off = (uint32_t)(aRow0 + mt * 16) * 128 +
                               (uint32_t)(((kk * 2 + aKU) ^ aSw) << 4);
                LDSM4(ahi[mt], s0 + off);
                LDSM4(alo[mt], s0 + 16384 + off);
            }
            // process 16 nt in two halves of 8 to bound live B fragments
#pragma unroll
            for (int half = 0; half < 2; ++half) {
                uint32_t bf[8][2];
#pragma unroll
                for (int p = 0; p < 4; ++p) {
                    uint32_t off = (uint32_t)(bN0 + half * 64 + p * 16) * 128 +
                                   (uint32_t)(((kk * 2 + bKU) ^ aSw) << 4);
                    uint32_t r[4];
                    LDSM4(r, s0 + 32768 + off);
                    bf[2 * p][0] = r[0]; bf[2 * p][1] = r[1];
                    bf[2 * p + 1][0] = r[2]; bf[2 * p + 1][1] = r[3];
                }
#pragma unroll
                for (int mt = 0; mt < 2; ++mt)
#pragma unroll
                    for (int q = 0; q < 8; ++q)
                        MMA(acc[mt][half * 8 + q], ahi[mt], bf[q]);
#pragma unroll
                for (int mt = 0; mt < 2; ++mt)
#pragma unroll
                    for (int q = 0; q < 8; ++q)
                        MMA(acc[mt][half * 8 + q], alo[mt], bf[q]);
            }
        }
        __syncthreads();
        buf ^= 1;
    }

    // ---- write Y (rows strided by 40*256 floats) ----
    const int rloc = wr * 32 + (lane >> 2);
    const int ecol = wc * 128 + (lane & 3) * 2;
#pragma unroll
    for (int mt = 0; mt < 2; ++mt)
#pragma unroll
        for (int h = 0; h < 2; ++h) {
            const int grow = (bg * 128 + rloc + mt * 16 + h * 8) * 40 + n;
            float* op = Y + (size_t)grow * 256;
#pragma unroll
            for (int nt = 0; nt < 16; ++nt)
                *(float2*)(op + ecol + nt * 8) =
                    make_float2(acc[mt][nt][2 * h], acc[mt][nt][2 * h + 1]);
        }

    // ---- fused column stats over this CTA's 128 rows ----
    float* st = (float*)smem;     // [8 warps][2 stats][128 cols]
    __syncthreads();
#pragma unroll
    for (int nt = 0; nt < 16; ++nt)
#pragma unroll
        for (int c = 0; c < 2; ++c) {
            float v0 = acc[0][nt][c],     v1 = acc[0][nt][2 + c];
            float v2 = acc[1][nt][c],     v3 = acc[1][nt][2 + c];
            float s  = (v0 + v1) + (v2 + v3);
            float s2 = fmaf(v0, v0, fmaf(v1, v1, fmaf(v2, v2, v3 * v3)));
#pragma unroll
            for (int m = 4; m <= 16; m <<= 1) {
                s  += __shfl_xor_sync(0xFFFFFFFF, s, m);
                s2 += __shfl_xor_sync(0xFFFFFFFF, s2, m);
            }
            if (lane < 4) {
                st[(wid * 2 + 0) * 128 + nt * 8 + lane * 2 + c] = s;
                st[(wid * 2 + 1) * 128 + nt * 8 + lane * 2 + c] = s2;
            }
        }
    __syncthreads();
    {
        const int col = tid;                  // 0..255
        const int wch = col >> 7, ci = col & 127;
        float ts = 0.f, ts2 = 0.f;
#pragma unroll
        for (int w = 0; w < 4; ++w) {
            ts  += st[((w * 2 + wch) * 2 + 0) * 128 + ci];
            ts2 += st[((w * 2 + wch) * 2 + 1) * 128 + ci];
        }
        float* gp = g_sp + (size_t)(n * 64 + bg) * 512;
        gp[col] = ts;
        gp[256 + col] = ts2;
    }
}

// ---------------------------------------------------------------------------
// K3b: fold bg partials -> scale/shift. grid 40, 256 threads.
// ---------------------------------------------------------------------------
__global__ void k3b_scaleshift(const float* __restrict__ gamma,
                               const float* __restrict__ beta) {
    const int n = blockIdx.x, col = threadIdx.x;
    float s = 0.f, s2 = 0.f;
#pragma unroll 4
    for (int bg = 0; bg < 64; ++bg) {
        const float* gp = g_sp + (size_t)(n * 64 + bg) * 512;
        s += gp[col];
        s2 += gp[256 + col];
    }
    const float inv = 1.f / (float)B_;
    float mean = s * inv;
    float var = fmaxf(s2 * inv - mean * mean, 0.f);
    int nf = n * 256 + col;
    int blk = n / 10;
    float sc = gamma[blk * NF + nf] * rsqrtf(var + 1e-5f);
    float bsum = beta[nf] + beta[NF + nf] + beta[2 * NF + nf] + beta[3 * NF + nf];
    g_scale[nf] = sc;
    g_shift[nf] = fmaf(-mean, sc, bsum);
}

// ---------------------------------------------------------------------------
// K4: out = Y * scale[nf] + shift[nf], float4.
// ---------------------------------------------------------------------------
__global__ void k4_normalize(float* __restrict__ Y) {
    const size_t gid = (size_t)blockIdx.x * blockDim.x + threadIdx.x;
    const int nf4 = (int)(gid % (NF / 4));
    float4 y = ((const float4*)Y)[gid];
    float4 sc = ((const float4*)g_scale)[nf4];
    float4 sh = ((const float4*)g_shift)[nf4];
    y.x = fmaf(y.x, sc.x, sh.x);
    y.y = fmaf(y.y, sc.y, sh.y);
    y.z = fmaf(y.z, sc.z, sh.z);
    y.w = fmaf(y.w, sc.w, sh.w);
    ((float4*)Y)[gid] = y;
}

// ---------------------------------------------------------------------------
extern "C" void kernel_launch(void* const* d_in, const int* in_sizes, int n_in,
                              void* d_out, int out_size) {
    const float* input = (const float*)d_in[0];
    const float* adj   = (const float*)d_in[1];
    const float* W     = (const float*)d_in[2];
    const float* gamma = (const float*)d_in[3];
    const float* beta  = (const float*)d_in[4];
    float* out = (float*)d_out;

    static bool attr_set = false;
    if (!attr_set) {
        cudaFuncSetAttribute(k2_gemm_stats, cudaFuncAttributeMaxDynamicSharedMemorySize, SMEM_K2);
        attr_set = true;
    }

    k0_wprep<<<256, 256>>>(W);
    k1_blockdiag<<<dim3(4, B_), 256>>>(input, adj);
    k2_gemm_stats<<<dim3(40, 64), 256, SMEM_K2>>>(out);
    k3b_scaleshift<<<40, 256>>>(gamma, beta);
    k4_normalize<<<(TOT / 4) / 256, 256>>>(out);
}

// round 7
// speedup vs baseline: 2.2592x; 1.0257x over previous
#include <cuda_runtime.h>
#include <cuda_fp16.h>
#include <cstdint>

#define B_   8192
#define N_   40
#define F_   256
#define NF   10240
#define TOT  83886080

// ---------------- device scratch (no allocation allowed) --------------------
__device__ __align__(256) __half g_Ahi[TOT];
__device__ __align__(256) __half g_Alo[TOT];
__device__ __align__(256) __half g_Yh[TOT];        // fp16 Y
__device__ __align__(256) __half g_Whi[F_ * F_];   // K-major [fout][fin]
__device__ float g_sp[40 * 64 * 2 * 256];          // [n][bg][stat][col]
__device__ float g_sp2[40 * 8 * 2 * 256];          // [n][y][stat][col]
__device__ float g_scale[NF];
__device__ float g_shift[NF];

// ---------------- helpers ---------------------------------------------------
__device__ __forceinline__ uint32_t smem_u32(const void* p) {
    uint32_t a;
    asm("{ .reg .u64 t; cvta.to.shared.u64 t, %1; cvt.u32.u64 %0, t; }" : "=r"(a) : "l"(p));
    return a;
}
__device__ __forceinline__ void cp16(uint32_t dst, const void* src) {
    asm volatile("cp.async.cg.shared.global [%0], [%1], 16;" :: "r"(dst), "l"(src));
}
#define CP_COMMIT() asm volatile("cp.async.commit_group;" ::: "memory")
#define CP_WAIT(n)  asm volatile("cp.async.wait_group %0;" :: "n"(n) : "memory")

#define LDSM4(r, addr)                                                          \
    asm volatile("ldmatrix.sync.aligned.m8n8.x4.shared.b16 {%0,%1,%2,%3}, [%4];"\
        : "=r"((r)[0]), "=r"((r)[1]), "=r"((r)[2]), "=r"((r)[3]) : "r"(addr))

#define MMA(c, a, b)                                                            \
    asm volatile("mma.sync.aligned.m16n8k16.row.col.f32.f16.f16.f32 "           \
        "{%0,%1,%2,%3}, {%4,%5,%6,%7}, {%8,%9}, {%0,%1,%2,%3};"                 \
        : "+f"((c)[0]), "+f"((c)[1]), "+f"((c)[2]), "+f"((c)[3])                \
        : "r"((a)[0]), "r"((a)[1]), "r"((a)[2]), "r"((a)[3]),                   \
          "r"((b)[0]), "r"((b)[1]))

// ---------------------------------------------------------------------------
// K0: W [fin][fout] fp32 -> fp16 K-major [fout][fin]
// ---------------------------------------------------------------------------
__global__ void k0_wprep(const float* __restrict__ W) {
    int k = blockIdx.x, n = threadIdx.x;
    g_Whi[n * 256 + k] = __float2half_rn(W[k * 256 + n]);
}

// ---------------------------------------------------------------------------
// K1: blockdiag bmm -> fp16 hi/lo.  grid (4, 2048) per batch-quarter.
// ---------------------------------------------------------------------------
__global__ void k1_blockdiag(const float* __restrict__ input,
                             const float* __restrict__ adj, int bofs) {
    const int b = bofs + blockIdx.y;
    const int s = blockIdx.x * 10;
    const int f = threadIdx.x;

    __shared__ float sadj[10][10];
    if (f < 100)
        sadj[f / 10][f % 10] = adj[((size_t)b * 40 + s + f / 10) * 40 + s + f % 10];
    __syncthreads();

    const float* ip = input + ((size_t)b * 40 + s) * 256 + f;
    float x[10];
#pragma unroll
    for (int c = 0; c < 10; ++c) x[c] = ip[c * 256];

    const size_t ob = ((size_t)b * 40 + s) * 256 + f;
#pragma unroll
    for (int r = 0; r < 10; ++r) {
        float acc = 0.f;
#pragma unroll
        for (int c = 0; c < 10; ++c) acc = fmaf(sadj[r][c], x[c], acc);
        __half h = __float2half_rn(acc);
        g_Ahi[ob + (size_t)r * 256] = h;
        g_Alo[ob + (size_t)r * 256] = __float2half_rn(acc - __half2float(h));
    }
}

// ---------------------------------------------------------------------------
// K2: fp16-split 2-pass HMMA GEMM (full 256 cols) + fused stats, fp16 Y out.
// CTA = (n, bg of 128 batches). grid (40, 16) per batch-quarter.
// ---------------------------------------------------------------------------
#define SMEM_K2 131072

__global__ __launch_bounds__(256, 1) void k2_gemm_stats(int bgofs) {
    extern __shared__ char smem[];
    const uint32_t sb = smem_u32(smem);
    const int tid = threadIdx.x, lane = tid & 31, wid = tid >> 5;
    const int wr = wid >> 1, wc = wid & 1;
    const int n = blockIdx.x;
    const int bg = bgofs + blockIdx.y;

    const char* aH = (const char*)g_Ahi + ((size_t)bg * 128 * 40 + n) * 512;
    const char* aL = (const char*)g_Alo + ((size_t)bg * 128 * 40 + n) * 512;
    const char* bB = (const char*)g_Whi;

    auto loadChunk = [&](int kcc, int buf) {
        const uint32_t s0 = sb + buf * 65536;
#pragma unroll
        for (int it = 0; it < 4; ++it) {
            int u = it * 256 + tid;
            int r = u >> 3, o = u & 7;
            size_t ga = (size_t)r * 20480 + (size_t)kcc * 128 + o * 16;
            uint32_t so = r * 128 + ((o ^ (r & 7)) << 4);
            cp16(s0 + so,         aH + ga);
            cp16(s0 + 16384 + so, aL + ga);
        }
#pragma unroll
        for (int it = 0; it < 8; ++it) {
            int u = it * 256 + tid;
            int r = u >> 3, o = u & 7;
            size_t gb = (size_t)r * 512 + (size_t)kcc * 128 + o * 16;
            uint32_t so = r * 128 + ((o ^ (r & 7)) << 4);
            cp16(s0 + 32768 + so, bB + gb);
        }
    };

    float acc[2][16][4];
#pragma unroll
    for (int mt = 0; mt < 2; ++mt)
#pragma unroll
        for (int nt = 0; nt < 16; ++nt)
#pragma unroll
            for (int q = 0; q < 4; ++q) acc[mt][nt][q] = 0.f;

    loadChunk(0, 0);
    CP_COMMIT();

    const int aRow0 = wr * 32 + (lane & 15);
    const int aKU = lane >> 4;
    const int aSw = lane & 7;
    const int bN0 = wc * 128 + (lane & 7) + ((lane >> 4) & 1) * 8;
    const int bKU = (lane >> 3) & 1;

    int buf = 0;
#pragma unroll
    for (int kcc = 0; kcc < 4; ++kcc) {
        if (kcc < 3) {
            loadChunk(kcc + 1, buf ^ 1);
            CP_COMMIT();
            CP_WAIT(1);
        } else {
            CP_WAIT(0);
        }
        __syncthreads();
        const uint32_t s0 = sb + buf * 65536;
#pragma unroll
        for (int kk = 0; kk < 4; ++kk) {
            uint32_t ahi[2][4], alo[2][4];
#pragma unroll
            for (int mt = 0; mt < 2; ++mt) {
                uint32_t off = (uint32_t)(aRow0 + mt * 16) * 128 +
                               (uint32_t)(((kk * 2 + aKU) ^ aSw) << 4);
                LDSM4(ahi[mt], s0 + off);
                LDSM4(alo[mt], s0 + 16384 + off);
            }
#pragma unroll
            for (int half = 0; half < 2; ++half) {
                uint32_t bf[8][2];
#pragma unroll
                for (int p = 0; p < 4; ++p) {
                    uint32_t off = (uint32_t)(bN0 + half * 64 + p * 16) * 128 +
                                   (uint32_t)(((kk * 2 + bKU) ^ aSw) << 4);
                    uint32_t r[4];
                    LDSM4(r, s0 + 32768 + off);
                    bf[2 * p][0] = r[0]; bf[2 * p][1] = r[1];
                    bf[2 * p + 1][0] = r[2]; bf[2 * p + 1][1] = r[3];
                }
#pragma unroll
                for (int mt = 0; mt < 2; ++mt)
#pragma unroll
                    for (int q = 0; q < 8; ++q)
                        MMA(acc[mt][half * 8 + q], ahi[mt], bf[q]);
#pragma unroll
                for (int mt = 0; mt < 2; ++mt)
#pragma unroll
                    for (int q = 0; q < 8; ++q)
                        MMA(acc[mt][half * 8 + q], alo[mt], bf[q]);
            }
        }
        __syncthreads();
        buf ^= 1;
    }

    // ---- epilogue: (a) stage fp16 Y in smem (swizzled), (b) stats partials --
    char* yst = smem + 8192;
    float* st = (float*)smem;     // [8 warps][2 stats][128 cols]  (8 KB)
    {
        const int rl = wr * 32 + (lane >> 2);
        const int cq = (lane & 3) * 2;
#pragma unroll
        for (int mt = 0; mt < 2; ++mt)
#pragma unroll
            for (int h = 0; h < 2; ++h) {
                const int row = rl + mt * 16 + h * 8;
                const uint32_t sw = (uint32_t)(row & 7) << 4;
#pragma unroll
                for (int nt = 0; nt < 16; ++nt) {
                    const int col = wc * 128 + nt * 8 + cq;
                    __half2 hv = __floats2half2_rn(acc[mt][nt][2 * h],
                                                   acc[mt][nt][2 * h + 1]);
                    *(__half2*)(yst + ((uint32_t)row * 512 + (((uint32_t)col * 2) ^ sw))) = hv;
                }
            }
    }
#pragma unroll
    for (int nt = 0; nt < 16; ++nt)
#pragma unroll
        for (int c = 0; c < 2; ++c) {
            float v0 = acc[0][nt][c],     v1 = acc[0][nt][2 + c];
            float v2 = acc[1][nt][c],     v3 = acc[1][nt][2 + c];
            float s  = (v0 + v1) + (v2 + v3);
            float s2 = fmaf(v0, v0, fmaf(v1, v1, fmaf(v2, v2, v3 * v3)));
#pragma unroll
            for (int m = 4; m <= 16; m <<= 1) {
                s  += __shfl_xor_sync(0xFFFFFFFF, s, m);
                s2 += __shfl_xor_sync(0xFFFFFFFF, s2, m);
            }
            if (lane < 4) {
                st[(wid * 2 + 0) * 128 + nt * 8 + lane * 2 + c] = s;
                st[(wid * 2 + 1) * 128 + nt * 8 + lane * 2 + c] = s2;
            }
        }
    __syncthreads();

    // ---- (c) coalesced fp16 Y copy-out: 128 rows x 512B ----
    {
        __half* yg = g_Yh + ((size_t)bg * 128 * 40 + n) * 256;
#pragma unroll
        for (int i = 0; i < 16; ++i) {
            int u = tid + 256 * i;
            int row = u >> 5, o = (u & 31) * 16;
            uint4 v = *(const uint4*)(yst + (uint32_t)row * 512 +
                                      ((uint32_t)o ^ ((uint32_t)(row & 7) << 4)));
            *(uint4*)((char*)(yg + (size_t)row * 40 * 256) + o) = v;
        }
    }
    // ---- (d) fold warp partials -> g_sp ----
    {
        const int col = tid;
        const int wch = col >> 7, ci = col & 127;
        float ts = 0.f, ts2 = 0.f;
#pragma unroll
        for (int w = 0; w < 4; ++w) {
            ts  += st[((w * 2 + wch) * 2 + 0) * 128 + ci];
            ts2 += st[((w * 2 + wch) * 2 + 1) * 128 + ci];
        }
        float* gp = g_sp + (size_t)(n * 64 + bg) * 512;
        gp[col] = ts;
        gp[256 + col] = ts2;
    }
}

// ---------------------------------------------------------------------------
// K3b1: partial fold over 8 bgs. grid (40, 8), 256 threads.
// ---------------------------------------------------------------------------
__global__ void k3b1_fold() {
    const int n = blockIdx.x, y = blockIdx.y, col = threadIdx.x;
    float s = 0.f, s2 = 0.f;
#pragma unroll
    for (int i = 0; i < 8; ++i) {
        const float* gp = g_sp + (size_t)(n * 64 + y * 8 + i) * 512;
        s += gp[col];
        s2 += gp[256 + col];
    }
    float* o = g_sp2 + (size_t)(n * 8 + y) * 512;
    o[col] = s;
    o[256 + col] = s2;
}

// K3b2: final fold -> scale/shift. grid 40, 256 threads.
__global__ void k3b2_scaleshift(const float* __restrict__ gamma,
                                const float* __restrict__ beta) {
    const int n = blockIdx.x, col = threadIdx.x;
    float s = 0.f, s2 = 0.f;
#pragma unroll
    for (int y = 0; y < 8; ++y) {
        const float* gp = g_sp2 + (size_t)(n * 8 + y) * 512;
        s += gp[col];
        s2 += gp[256 + col];
    }
    const float inv = 1.f / (float)B_;
    float mean = s * inv;
    float var = fmaxf(s2 * inv - mean * mean, 0.f);
    int nf = n * 256 + col;
    int blk = n / 10;
    float sc = gamma[blk * NF + nf] * rsqrtf(var + 1e-5f);
    float bsum = beta[nf] + beta[NF + nf] + beta[2 * NF + nf] + beta[3 * NF + nf];
    g_scale[nf] = sc;
    g_shift[nf] = fmaf(-mean, sc, bsum);
}

// ---------------------------------------------------------------------------
// K4: out = Yh * scale + shift (fp16 read, fp32 write). 8 elems/thread.
// ---------------------------------------------------------------------------
__global__ void k4_normalize(float* __restrict__ out) {
    const size_t gid = (size_t)blockIdx.x * blockDim.x + threadIdx.x;  // < TOT/8
    uint4 raw = ((const uint4*)g_Yh)[gid];
    const int col8 = (int)(gid & 31);
    const int grow = (int)(gid >> 5);
    const int n = grow % 40;
    const float* scp = g_scale + n * 256 + col8 * 8;
    const float* shp = g_shift + n * 256 + col8 * 8;
    float4 sc0 = *(const float4*)scp, sc1 = *(const float4*)(scp + 4);
    float4 sh0 = *(const float4*)shp, sh1 = *(const float4*)(shp + 4);
    const __half2* hp = (const __half2*)&raw;
    float2 f0 = __half22float2(hp[0]);
    float2 f1 = __half22float2(hp[1]);
    float2 f2 = __half22float2(hp[2]);
    float2 f3 = __half22float2(hp[3]);
    float4 o0, o1;
    o0.x = fmaf(f0.x, sc0.x, sh0.x);
    o0.y = fmaf(f0.y, sc0.y, sh0.y);
    o0.z = fmaf(f1.x, sc0.z, sh0.z);
    o0.w = fmaf(f1.y, sc0.w, sh0.w);
    o1.x = fmaf(f2.x, sc1.x, sh1.x);
    o1.y = fmaf(f2.y, sc1.y, sh1.y);
    o1.z = fmaf(f3.x, sc1.z, sh1.z);
    o1.w = fmaf(f3.y, sc1.w, sh1.w);
    float* op = out + (size_t)grow * 256 + col8 * 8;
    *(float4*)op = o0;
    *(float4*)(op + 4) = o1;
}

// ---------------------------------------------------------------------------
extern "C" void kernel_launch(void* const* d_in, const int* in_sizes, int n_in,
                              void* d_out, int out_size) {
    const float* input = (const float*)d_in[0];
    const float* adj   = (const float*)d_in[1];
    const float* W     = (const float*)d_in[2];
    const float* gamma = (const float*)d_in[3];
    const float* beta  = (const float*)d_in[4];
    float* out = (float*)d_out;

    static bool inited = false;
    static cudaStream_t s2;
    static cudaEvent_t ev1[4], ev2;
    if (!inited) {
        cudaFuncSetAttribute(k2_gemm_stats, cudaFuncAttributeMaxDynamicSharedMemorySize, SMEM_K2);
        cudaStreamCreateWithFlags(&s2, cudaStreamNonBlocking);
        for (int j = 0; j < 4; ++j)
            cudaEventCreateWithFlags(&ev1[j], cudaEventDisableTiming);
        cudaEventCreateWithFlags(&ev2, cudaEventDisableTiming);
        inited = true;
    }

    k0_wprep<<<256, 256>>>(W);
    for (int j = 0; j < 4; ++j) {
        k1_blockdiag<<<dim3(4, 2048), 256>>>(input, adj, j * 2048);
        cudaEventRecord(ev1[j], 0);
        cudaStreamWaitEvent(s2, ev1[j], 0);
        k2_gemm_stats<<<dim3(40, 16), 256, SMEM_K2, s2>>>(j * 16);
    }
    cudaEventRecord(ev2, s2);
    cudaStreamWaitEvent(0, ev2, 0);
    k3b1_fold<<<dim3(40, 8), 256>>>();
    k3b2_scaleshift<<<40, 256>>>(gamma, beta);
    k4_normalize<<<(TOT / 8) / 256, 256>>>(out);
}